// round 15
// baseline (speedup 1.0000x reference)
#include <cuda_runtime.h>
#include <cstdint>

// BinLinear: out = input @ sign(tanh(weight)), weight_b in {-1,+1}.
// Identity: out[n,o] = S[n] - 2*T[n,o], S[n]=rowsum(input row n),
//           T[n,o]  = sum of x[n,k] over k where weight[k,o] < 0.
// Exact fp32 products; only summation order differs from reference.
//
// R15: PDL done properly. Mega triggers programmatic launch completion at
// the TOP (R14 triggered at the end, so the secondary's ramp stayed
// serialized). The fixup grid launches while mega streams and runs a real
// PREAMBLE — the last 1024 rowfill rows — before parking at
// cudaGridDependencySynchronize(). After mega completes (+ memory flush,
// guaranteed by the gridsync regardless of trigger placement), fixup reads
// g_anyflag and exits (dataset case) or applies exact corrections.
//
// Shapes fixed: M=8192, K=2048 (num_ip), N=2048 (num_op).

#define MDIM 8192
#define KDIM 2048
#define NDIM 2048
#define NQ   (NDIM / 4)      // 512 column quads
#define KB   (KDIM / 8)      // 256 k-groups of 8 (32-bit mask words)
#define FULL 0xffffffffu

#define MEGA_GRID  1408      // 128 groups of 11: 7 rowfill + 4 binarize
#define MEGA_ROWS  7168      // rows handled by mega (896 blocks x 8)
#define FIX_BLOCKS 128       // preamble: rows 7168..8191 (128 blocks x 8)

// Scratch (no cudaMalloc). Zero-initialized; mask writes value-identical
// across replays, OR-atomics idempotent -> replay-deterministic.
// g_mask[kb*NQ + c4]: bit (j*4+e) = sign of weight[kb*8+j][c4*4+e] (1 => -1).
__device__ uint32_t g_mask[KB * NQ];     // 512 KB
__device__ uint32_t g_negq[NQ];          // per-quad OR of mask words (rare path)
__device__ uint32_t g_anyflag;           // nonzero iff any negative weight
__device__ float    g_S[MDIM];           // row sums (mega-owned rows)

// Shared rowfill body: one warp per row, one-pass read -> S -> write.
__device__ __forceinline__ void rowfill_row(const float* __restrict__ x,
                                            float* __restrict__ out,
                                            int row, int lane, bool write_S) {
    const float4* xrow4 = (const float4*)(x + (size_t)row * KDIM);
    float s = 0.0f;
    #pragma unroll
    for (int half = 0; half < 2; half++) {           // 2 batches of 8 in flight
        float4 v[8];
        #pragma unroll
        for (int i = 0; i < 8; i++)
            v[i] = __ldcs(&xrow4[lane + 32 * (half * 8 + i)]);
        #pragma unroll
        for (int i = 0; i < 8; i++)
            s += (v[i].x + v[i].y) + (v[i].z + v[i].w);
    }
    #pragma unroll
    for (int ofs = 16; ofs; ofs >>= 1)
        s += __shfl_xor_sync(FULL, s, ofs);          // all lanes hold S
    if (write_S && lane == 0) g_S[row] = s;

    float4 val = make_float4(s, s, s, s);
    float4* orow4 = (float4*)(out + (size_t)row * NDIM);
    #pragma unroll
    for (int i = 0; i < 16; i++)
        orow4[lane + 32 * i] = val;                  // plain stores -> L2
}

// ---------------------------------------------------------------------------
// Mega kernel: 1408 blocks, 7 rowfill : 4 binarize per group of 11.
// Triggers PDL completion immediately; the gridsync in fixup still waits
// for full completion + flush, so correctness is unaffected.
// ---------------------------------------------------------------------------
__global__ void __launch_bounds__(256) mega_kernel(const float4* __restrict__ w4,
                                                   const float* __restrict__ x,
                                                   float* __restrict__ out) {
    cudaTriggerProgrammaticLaunchCompletion();       // let fixup start its preamble

    int bid = blockIdx.x;
    int grp = bid / 11;
    int rem = bid - grp * 11;

    if (rem < 7) {
        // ---- rowfill: rows 0..7167 ----
        int rb = grp * 7 + rem;                      // 0..895
        rowfill_row(x, out, rb * 8 + (threadIdx.x >> 5), threadIdx.x & 31, true);
    } else {
        // ---- binarize: thread owns (quad c4, 8 k's) ----
        int bb  = grp * 4 + (rem - 7);               // 0..511
        int tid = bb * 256 + threadIdx.x;            // 0..131071
        int c4  = tid & (NQ - 1);                    // fastest -> coalesced
        int kb  = tid >> 9;                          // 0..255
        const float4* base = w4 + (size_t)(kb * 8) * NQ + c4;

        uint32_t bits = 0;
        #pragma unroll
        for (int j = 0; j < 8; j++) {
            float4 v = __ldcs(&base[(size_t)j * NQ]);
            uint32_t b = (uint32_t)(v.x < 0.0f)
                       | ((uint32_t)(v.y < 0.0f) << 1)
                       | ((uint32_t)(v.z < 0.0f) << 2)
                       | ((uint32_t)(v.w < 0.0f) << 3);
            bits |= b << (j * 4);
        }
        g_mask[kb * NQ + c4] = bits;                 // coalesced word store

        if (bits) {                                  // rare path (idempotent)
            atomicOr(&g_negq[c4], bits);
            atomicOr(&g_anyflag, 1u);
        }
    }
}

// ---------------------------------------------------------------------------
// Fixup (PDL secondary). Preamble: rowfill rows 7168..8191 (independent of
// mega -> runs concurrently with it). Then gridsync (mega complete +
// visible), flag check, and — only if negatives exist — exact corrections:
// out[n, c] = S - 2*T recomputed from input + mask. For preamble-owned rows
// (>= MEGA_ROWS) S is recomputed from the input row, since g_S visibility
// across fixup's own blocks is not guaranteed.
// ---------------------------------------------------------------------------
__global__ void __launch_bounds__(256) fixup_kernel(const float* __restrict__ x,
                                                    float* __restrict__ out) {
    // Preamble: independent streaming work overlapping mega.
    rowfill_row(x, out, MEGA_ROWS + blockIdx.x * 8 + (threadIdx.x >> 5),
                threadIdx.x & 31, false);

    cudaGridDependencySynchronize();                 // mega complete + visible

    if (g_anyflag == 0) return;                      // dataset case: done

    for (int c4 = blockIdx.x; c4 < NQ; c4 += FIX_BLOCKS) {
        uint32_t q = g_negq[c4];
        if (q == 0) continue;
        for (int n = threadIdx.x; n < MDIM; n += 256) {
            const float* xrow = x + (size_t)n * KDIM;
            float s;
            if (n < MEGA_ROWS) {
                s = g_S[n];                          // mega's, visible post-sync
            } else {
                s = 0.0f;                            // recompute (rare path)
                for (int k = 0; k < KDIM; k++) s += xrow[k];
            }
            #pragma unroll
            for (int e = 0; e < 4; e++) {
                if ((q >> e) & 0x11111111u) {
                    float T = 0.0f;
                    for (int kb = 0; kb < KB; kb++) {
                        uint32_t word = g_mask[kb * NQ + c4];
                        uint32_t sel = (word >> e) & 0x11111111u;
                        while (sel) {
                            int b = __ffs(sel) - 1;  // b = j*4
                            sel &= sel - 1;
                            T += xrow[kb * 8 + (b >> 2)];
                        }
                    }
                    out[(size_t)n * NDIM + c4 * 4 + e] = s - 2.0f * T;
                }
            }
        }
    }
}

extern "C" void kernel_launch(void* const* d_in, const int* in_sizes, int n_in,
                              void* d_out, int out_size) {
    const float* input  = (const float*)d_in[0];   // [8192, 2048]
    const float* weight = (const float*)d_in[1];   // [2048, 2048]
    float* out = (float*)d_out;                    // [8192, 2048]

    mega_kernel<<<MEGA_GRID, 256>>>((const float4*)weight, input, out);

    // Fixup with Programmatic Dependent Launch: launches during mega,
    // preamble overlaps mega's streaming, gridsync orders the rest.
    cudaLaunchConfig_t cfg = {};
    cfg.gridDim  = dim3(FIX_BLOCKS, 1, 1);
    cfg.blockDim = dim3(256, 1, 1);
    cfg.dynamicSmemBytes = 0;
    cudaLaunchAttribute attrs[1];
    attrs[0].id = cudaLaunchAttributeProgrammaticStreamSerialization;
    attrs[0].val.programmaticStreamSerializationAllowed = 1;
    cfg.attrs = attrs;
    cfg.numAttrs = 1;
    cudaLaunchKernelEx(&cfg, fixup_kernel, input, out);
}